// round 1
// baseline (speedup 1.0000x reference)
#include <cuda_runtime.h>
#include <cstdint>

// Problem constants (fixed shapes from setup_inputs)
#define BB   16
#define NN   1536
#define CC   768
#define N0   3072
#define HH   64
#define WW   48
#define HW   (HH*WW)            // 3072
#define FM   (BB*HW*CC)         // 37,748,736 floats
#define NPTS (BB*N0)            // 49,152
#define EPSF 1e-6f

// Scratch (device globals: allocation-free, per harness rules)
__device__ __align__(16) float g_raw [FM];       // token2map accumulation, [B][HW][C]
__device__ __align__(16) float g_conv[FM];       // post-conv map,          [B][HW][C]
__device__ __align__(16) float g_cnt [BB*HW];    // hit count -> 1/(cnt+eps)
__device__ __align__(16) float g_wsum[BB*NN];    // sum(agg_w) -> 1/(sum+eps)
__device__ __align__(16) float g_wT  [9*CC];     // conv weights transposed [k][C]

__device__ __forceinline__ void red_add4(float* p, float4 v) {
    asm volatile("red.global.add.v4.f32 [%0], {%1,%2,%3,%4};"
                 :: "l"(p), "f"(v.x), "f"(v.y), "f"(v.z), "f"(v.w) : "memory");
}

// pixel coords matching jnp: pos = 0.5*(clip(loc,-1,1)+1)*wh - 0.5, unfused to match rounding
__device__ __forceinline__ float pix_coord(float l, float wh) {
    l = fminf(fmaxf(l, -1.0f), 1.0f);
    float t = __fmul_rn(0.5f, __fadd_rn(l, 1.0f));
    return __fadd_rn(__fmul_rn(t, wh), -0.5f);
}

// ---------------- zeroing ----------------
__global__ void k_zero_scratch() {
    const int n_raw4 = FM/4, n_cnt4 = (BB*HW)/4, n_ws4 = (BB*NN)/4;
    int i = blockIdx.x * blockDim.x + threadIdx.x;
    float4 z = make_float4(0.f, 0.f, 0.f, 0.f);
    if (i < n_raw4)                       ((float4*)g_raw )[i] = z;
    else if (i < n_raw4 + n_cnt4)         ((float4*)g_cnt )[i - n_raw4] = z;
    else if (i < n_raw4 + n_cnt4 + n_ws4) ((float4*)g_wsum)[i - n_raw4 - n_cnt4] = z;
}

__global__ void k_zero_out(float4* out, int n4) {
    int i = blockIdx.x * blockDim.x + threadIdx.x;
    if (i < n4) out[i] = make_float4(0.f, 0.f, 0.f, 0.f);
}

// ---------------- counts + weight sums ----------------
__global__ void k_count(const float* __restrict__ loc_orig,
                        const int*   __restrict__ idx_agg,
                        const float* __restrict__ agg_w) {
    int p = blockIdx.x * blockDim.x + threadIdx.x;
    if (p >= NPTS) return;
    int b = p / N0;
    float px = pix_coord(loc_orig[2*p],   (float)WW);
    float py = pix_coord(loc_orig[2*p+1], (float)HH);
    int ix = min(max((int)rintf(px), 0), WW-1);   // rintf = round-half-even = jnp.round
    int iy = min(max((int)rintf(py), 0), HH-1);
    atomicAdd(&g_cnt[b*HW + iy*WW + ix], 1.0f);
    int tok = idx_agg[p];
    atomicAdd(&g_wsum[b*NN + tok], agg_w[p]);
}

// ---------------- reciprocals + weight transpose ----------------
__global__ void k_prep(const float* __restrict__ conv_w) {
    int i = blockIdx.x * blockDim.x + threadIdx.x;
    if (i < 9*CC) {
        int c = i / 9, k = i % 9;           // conv_w layout [C][1][3][3]
        g_wT[k*CC + c] = conv_w[i];
    } else if (i < 9*CC + BB*HW) {
        int j = i - 9*CC;
        g_cnt[j] = 1.0f / (g_cnt[j] + EPSF);
    } else if (i < 9*CC + BB*HW + BB*NN) {
        int j = i - 9*CC - BB*HW;
        g_wsum[j] = 1.0f / (g_wsum[j] + EPSF);
    }
}

// ---------------- feature scatter: x[b, idx_agg] -> raw map ----------------
__global__ __launch_bounds__(192) void k_scatter(const float* __restrict__ x,
                                                 const float* __restrict__ loc_orig,
                                                 const int*   __restrict__ idx_agg) {
    int p = blockIdx.x;
    int b = p / N0;
    float px = pix_coord(loc_orig[2*p],   (float)WW);
    float py = pix_coord(loc_orig[2*p+1], (float)HH);
    int ix = min(max((int)rintf(px), 0), WW-1);
    int iy = min(max((int)rintf(py), 0), HH-1);
    int pix = b*HW + iy*WW + ix;
    int tok = idx_agg[p];
    const float4* src = (const float4*)(x + ((size_t)b*NN + tok)*CC);
    float* dst = g_raw + (size_t)pix*CC;
    int c4 = threadIdx.x;                    // 192 threads, C/4 = 192
    float4 v = src[c4];
    red_add4(dst + 4*c4, v);
}

// ---------------- depthwise 3x3 conv with count-normalization folded in ----------------
__global__ __launch_bounds__(192) void k_conv(const float* __restrict__ conv_b) {
    int gp = blockIdx.x;                     // B*HW pixels
    int b  = gp / HW;
    int hw = gp - b*HW;
    int y  = hw / WW;
    int xx = hw - y*WW;
    int c4 = threadIdx.x;
    float4 acc = ((const float4*)conv_b)[c4];
    #pragma unroll
    for (int dy = -1; dy <= 1; dy++) {
        #pragma unroll
        for (int dx = -1; dx <= 1; dx++) {
            int ny = y + dy, nx = xx + dx;
            if (ny < 0 || ny >= HH || nx < 0 || nx >= WW) continue;
            int np = b*HW + ny*WW + nx;
            float rc = __ldg(&g_cnt[np]);
            int k = (dy+1)*3 + (dx+1);
            float4 v  = *(const float4*)(g_raw + (size_t)np*CC + 4*c4);
            float4 wv = *(const float4*)(g_wT  + k*CC          + 4*c4);
            acc.x += v.x * rc * wv.x;
            acc.y += v.y * rc * wv.y;
            acc.z += v.z * rc * wv.z;
            acc.w += v.w * rc * wv.w;
        }
    }
    *(float4*)(g_conv + (size_t)gp*CC + 4*c4) = acc;
}

// ---------------- bilinear gather + weighted scatter to tokens ----------------
__global__ __launch_bounds__(192) void k_gather(const float* __restrict__ loc_orig,
                                                const int*   __restrict__ idx_agg,
                                                const float* __restrict__ agg_w,
                                                float*       __restrict__ out) {
    int p = blockIdx.x;
    int b = p / N0;
    float px = pix_coord(loc_orig[2*p],   (float)WW);
    float py = pix_coord(loc_orig[2*p+1], (float)HH);
    int x0 = min(max((int)floorf(px), 0), WW-1);
    int y0 = min(max((int)floorf(py), 0), HH-1);
    int x1 = min(x0 + 1, WW-1);
    int y1 = min(y0 + 1, HH-1);
    float wx = fminf((float)x1, px) - (float)x0;   // replicates reference border quirk
    float wy = fminf((float)y1, py) - (float)y0;
    float w00 = (1.0f-wx)*(1.0f-wy);
    float w10 = wx*(1.0f-wy);
    float w01 = (1.0f-wx)*wy;
    float w11 = wx*wy;
    int base = b*HW;
    const float4* f00 = (const float4*)(g_conv + (size_t)(base + y0*WW + x0)*CC);
    const float4* f10 = (const float4*)(g_conv + (size_t)(base + y0*WW + x1)*CC);
    const float4* f01 = (const float4*)(g_conv + (size_t)(base + y1*WW + x0)*CC);
    const float4* f11 = (const float4*)(g_conv + (size_t)(base + y1*WW + x1)*CC);
    int tok = idx_agg[p];
    float scale = agg_w[p] * g_wsum[b*NN + tok];   // w / (wsum + eps)
    float* dst = out + ((size_t)b*NN + tok)*CC;
    int c4 = threadIdx.x;
    float4 a = f00[c4], bq = f10[c4], cq = f01[c4], dq = f11[c4];
    float4 v;
    v.x = (w00*a.x + w10*bq.x + w01*cq.x + w11*dq.x) * scale;
    v.y = (w00*a.y + w10*bq.y + w01*cq.y + w11*dq.y) * scale;
    v.z = (w00*a.z + w10*bq.z + w01*cq.z + w11*dq.z) * scale;
    v.w = (w00*a.w + w10*bq.w + w01*cq.w + w11*dq.w) * scale;
    red_add4(dst + 4*c4, v);
}

// ---------------- launch ----------------
extern "C" void kernel_launch(void* const* d_in, const int* in_sizes, int n_in,
                              void* d_out, int out_size) {
    const float* x        = (const float*)d_in[0];
    const float* loc_orig = (const float*)d_in[2];
    const int*   idx_agg  = (const int*)  d_in[3];
    const float* agg_w    = (const float*)d_in[4];
    const float* conv_w   = (const float*)d_in[n_in-2];
    const float* conv_b   = (const float*)d_in[n_in-1];
    float* out = (float*)d_out;

    // zero scratch + output
    {
        int total4 = FM/4 + (BB*HW)/4 + (BB*NN)/4;
        k_zero_scratch<<<(total4 + 255)/256, 256>>>();
        int n4 = out_size / 4;
        k_zero_out<<<(n4 + 255)/256, 256>>>((float4*)out, n4);
    }
    // per-pixel counts + per-token weight sums
    k_count<<<(NPTS + 255)/256, 256>>>(loc_orig, idx_agg, agg_w);
    // reciprocals + weight transpose
    {
        int total = 9*CC + BB*HW + BB*NN;
        k_prep<<<(total + 255)/256, 256>>>(conv_w);
    }
    // feature scatter to map
    k_scatter<<<NPTS, 192>>>(x, loc_orig, idx_agg);
    // depthwise conv (normalization folded)
    k_conv<<<BB*HW, 192>>>(conv_b);
    // bilinear gather + token aggregation
    k_gather<<<NPTS, 192>>>(loc_orig, idx_agg, agg_w, out);
}